// round 3
// baseline (speedup 1.0000x reference)
#include <cuda_runtime.h>
#include <cuda_bf16.h>
#include <cstdint>

#define N_NODES 50000
#define N_EDGES 800000
#define N_GRAPHS 128
#define ROWS (N_NODES * 4)          // 200000 token rows of width 64
#define NODE_F 256                  // floats per node (4 x 64)

// ---------------- scratch (device globals: no allocs allowed) ----------------
__device__ __align__(16) float g_h[N_NODES * NODE_F];     // current hidden state
__device__ __align__(16) float g_agg[N_NODES * NODE_F];   // aggregation buffer
__device__ __align__(16) float g_hpre[N_NODES * NODE_F];  // LN1(h) gather source
__device__ __align__(16) float g_pooled[4 * N_GRAPHS * NODE_F];

// ---------------- vector global reductions (sm_90+) ----------------
__device__ __forceinline__ void red_add_f4(float* addr, float4 v) {
    asm volatile("red.global.add.v4.f32 [%0], {%1,%2,%3,%4};"
                 :: "l"(addr), "f"(v.x), "f"(v.y), "f"(v.z), "f"(v.w) : "memory");
}
__device__ __forceinline__ void red_add_f2(float* addr, float2 v) {
    asm volatile("red.global.add.v2.f32 [%0], {%1,%2};"
                 :: "l"(addr), "f"(v.x), "f"(v.y) : "memory");
}

// ---------------- tiny utility kernels ----------------
__global__ void zero_pooled_kernel() {
    int i = blockIdx.x * blockDim.x + threadIdx.x;
    if (i < 4 * N_GRAPHS * NODE_F) g_pooled[i] = 0.0f;
}

__global__ void copy_to_agg_kernel(const float4* __restrict__ src) {
    int i = blockIdx.x * blockDim.x + threadIdx.x;
    if (i < N_NODES * 64) ((float4*)g_agg)[i] = __ldg(src + i);
}

// pooled[0] += segment_sum(feat) (hidden_rep[0] is raw features)
__global__ void pool_raw_kernel(const float4* __restrict__ feat,
                                const int* __restrict__ gids) {
    int i = blockIdx.x * blockDim.x + threadIdx.x;
    if (i >= N_NODES * 64) return;
    int n = i >> 6, r = i & 63;
    int gid = __ldg(gids + n);
    float4 v = __ldg(feat + i);
    red_add_f4((float*)(((float4*)g_pooled) + gid * 64 + r), v);
}

// ---------------- edge scatter-add: agg[dst] += hsrc[src] ----------------
// one warp per edge; each lane moves 2 float4 (256 floats/edge)
__global__ void edge_kernel(const float* __restrict__ hsrc,
                            const int* __restrict__ src,
                            const int* __restrict__ dst) {
    int w = (blockIdx.x * blockDim.x + threadIdx.x) >> 5;
    int lane = threadIdx.x & 31;
    if (w >= N_EDGES) return;
    int s = __ldg(src + w);
    int d = __ldg(dst + w);
    const float4* ps = (const float4*)hsrc + (size_t)s * 64;
    float4* pd = (float4*)g_agg + (size_t)d * 64;
    float4 a = __ldg(ps + lane);
    float4 b = __ldg(ps + lane + 32);
    red_add_f4((float*)(pd + lane), a);
    red_add_f4((float*)(pd + lane + 32), b);
}

// ---------------- LN1 prep: g_hpre = g_agg = layer_norm(g_h) ----------------
// one warp per 64-wide row; 2 floats per lane
__global__ void ln_prep_kernel(const float* __restrict__ gw,
                               const float* __restrict__ bw) {
    int w = (blockIdx.x * blockDim.x + threadIdx.x) >> 5;
    int lane = threadIdx.x & 31;
    if (w >= ROWS) return;
    float2 x = __ldg((const float2*)g_h + (size_t)w * 32 + lane);
    float sum = x.x + x.y, sq = x.x * x.x + x.y * x.y;
#pragma unroll
    for (int o = 16; o; o >>= 1) {
        sum += __shfl_xor_sync(0xFFFFFFFFu, sum, o);
        sq  += __shfl_xor_sync(0xFFFFFFFFu, sq, o);
    }
    float mu = sum * (1.0f / 64.0f);
    float rstd = rsqrtf(sq * (1.0f / 64.0f) - mu * mu + 1e-5f);
    int d = lane * 2;
    float2 y;
    y.x = (x.x - mu) * rstd * __ldg(gw + d) + __ldg(bw + d);
    y.y = (x.y - mu) * rstd * __ldg(gw + d + 1) + __ldg(bw + d + 1);
    ((float2*)g_hpre)[(size_t)w * 32 + lane] = y;
    ((float2*)g_agg)[(size_t)w * 32 + lane] = y;
}

// ---------------- pooled[layer] += segment_sum(layer_norm(relu(g_h))) ----------------
__global__ void pool_lnrelu_kernel(const float* __restrict__ gw,
                                   const float* __restrict__ bw,
                                   const int* __restrict__ gids,
                                   int layer) {
    int w = (blockIdx.x * blockDim.x + threadIdx.x) >> 5;
    int lane = threadIdx.x & 31;
    if (w >= ROWS) return;
    float2 x = __ldg((const float2*)g_h + (size_t)w * 32 + lane);
    x.x = fmaxf(x.x, 0.0f);
    x.y = fmaxf(x.y, 0.0f);
    float sum = x.x + x.y, sq = x.x * x.x + x.y * x.y;
#pragma unroll
    for (int o = 16; o; o >>= 1) {
        sum += __shfl_xor_sync(0xFFFFFFFFu, sum, o);
        sq  += __shfl_xor_sync(0xFFFFFFFFu, sq, o);
    }
    float mu = sum * (1.0f / 64.0f);
    float rstd = rsqrtf(sq * (1.0f / 64.0f) - mu * mu + 1e-5f);
    int d = lane * 2;
    float2 y;
    y.x = (x.x - mu) * rstd * __ldg(gw + d) + __ldg(bw + d);
    y.y = (x.y - mu) * rstd * __ldg(gw + d + 1) + __ldg(bw + d + 1);
    int n = w >> 2, s = w & 3;
    int gid = __ldg(gids + n);
    float* base = g_pooled + (size_t)layer * (N_GRAPHS * NODE_F) + gid * NODE_F + s * 64;
    red_add_f2(base + d, y);
}

// ---------------- fused SAB block ----------------
// x = g_agg; xin = LN(x); q,k,v = xin @ W*; att softmax over S=4; o @ Wo; residuals.
// 16 nodes/block, 16 threads/node (each thread owns 4 of 64 output columns).
// RES=false: g_h = oWo.  RES=true: g_h = g_h + oWo + g_agg.
#define SAB_SMEM_FLOATS (4 * 4096 + 128 + 16 * 264)

template <bool RES>
__global__ void __launch_bounds__(256)
sab_kernel(const float* __restrict__ Wq, const float* __restrict__ Wk,
           const float* __restrict__ Wv, const float* __restrict__ Wo,
           const float* __restrict__ lng, const float* __restrict__ lnb) {
    extern __shared__ float sm[];
    float* sWq = sm;
    float* sWk = sm + 4096;
    float* sWv = sm + 8192;
    float* sWo = sm + 12288;
    float* sLg = sm + 16384;
    float* sLb = sm + 16448;
    float* sX  = sm + 16512;   // 16 nodes, stride 264 floats (bank-skewed)

    int tid = threadIdx.x;
    int nodeBase = blockIdx.x * 16;

    // stage weights
    {
        float4* d4 = (float4*)sWq;
#pragma unroll
        for (int i = tid; i < 1024; i += 256) {
            d4[i]        = __ldg((const float4*)Wq + i);
            d4[1024 + i] = __ldg((const float4*)Wk + i);
            d4[2048 + i] = __ldg((const float4*)Wv + i);
            d4[3072 + i] = __ldg((const float4*)Wo + i);
        }
        if (tid < 64) {
            sLg[tid] = __ldg(lng + tid);
            sLb[tid] = __ldg(lnb + tid);
        }
    }
    // stage x tile (swizzled node stride 264)
    {
        const float4* srcp = (const float4*)g_agg + (size_t)nodeBase * 64;
        float4* sx4 = (float4*)sX;
#pragma unroll
        for (int i = tid; i < 1024; i += 256) {
            int n = i >> 6, r = i & 63;
            sx4[n * 66 + r] = __ldg(srcp + i);
        }
    }
    __syncthreads();

    int nl = tid >> 4;       // node within block
    int t  = tid & 15;       // thread within node
    float* xrow = sX + nl * 264;

    // in-place LayerNorm of the 4 rows: thread handles (row s, quarter qq)
    {
        int s = t & 3, qq = t >> 2;
        float sum = 0.f, sq = 0.f;
#pragma unroll
        for (int c = 0; c < 16; c++) {
            float xv = xrow[s * 64 + qq * 16 + c];
            sum += xv; sq += xv * xv;
        }
        sum += __shfl_xor_sync(0xFFFFFFFFu, sum, 4);
        sq  += __shfl_xor_sync(0xFFFFFFFFu, sq, 4);
        sum += __shfl_xor_sync(0xFFFFFFFFu, sum, 8);
        sq  += __shfl_xor_sync(0xFFFFFFFFu, sq, 8);
        float mu = sum * (1.0f / 64.0f);
        float rstd = rsqrtf(sq * (1.0f / 64.0f) - mu * mu + 1e-5f);
#pragma unroll
        for (int c = 0; c < 16; c++) {
            int d = qq * 16 + c;
            float xv = xrow[s * 64 + d];
            xrow[s * 64 + d] = (xv - mu) * rstd * sLg[d] + sLb[d];
        }
    }
    __syncwarp();

    // projections: q,k,v for this thread's 4 columns (j0..j0+3), all 4 rows
    int j0 = t * 4;
    float q[4][4], k[4][4], v[4][4];
#pragma unroll
    for (int s = 0; s < 4; s++)
#pragma unroll
        for (int c = 0; c < 4; c++) { q[s][c] = 0.f; k[s][c] = 0.f; v[s][c] = 0.f; }

#pragma unroll 4
    for (int d = 0; d < 64; d++) {
        float4 wq = *(const float4*)(sWq + d * 64 + j0);
        float4 wk = *(const float4*)(sWk + d * 64 + j0);
        float4 wv = *(const float4*)(sWv + d * 64 + j0);
#pragma unroll
        for (int s = 0; s < 4; s++) {
            float xv = xrow[s * 64 + d];
            q[s][0] += xv * wq.x; q[s][1] += xv * wq.y; q[s][2] += xv * wq.z; q[s][3] += xv * wq.w;
            k[s][0] += xv * wk.x; k[s][1] += xv * wk.y; k[s][2] += xv * wk.z; k[s][3] += xv * wk.w;
            v[s][0] += xv * wv.x; v[s][1] += xv * wv.y; v[s][2] += xv * wv.z; v[s][3] += xv * wv.w;
        }
    }
    // scale q by 1/sqrt(dk)=1/4
#pragma unroll
    for (int s = 0; s < 4; s++)
#pragma unroll
        for (int c = 0; c < 4; c++) q[s][c] *= 0.25f;

    // attention scores: head = t/4 owns 16 dims split across 4 threads -> shfl reduce
    float att[4][4];
#pragma unroll
    for (int qi = 0; qi < 4; qi++)
#pragma unroll
        for (int si = 0; si < 4; si++) {
            float p = q[qi][0] * k[si][0] + q[qi][1] * k[si][1] +
                      q[qi][2] * k[si][2] + q[qi][3] * k[si][3];
            p += __shfl_xor_sync(0xFFFFFFFFu, p, 1);
            p += __shfl_xor_sync(0xFFFFFFFFu, p, 2);
            att[qi][si] = p;
        }
    // softmax over si
#pragma unroll
    for (int qi = 0; qi < 4; qi++) {
        float m = fmaxf(fmaxf(att[qi][0], att[qi][1]), fmaxf(att[qi][2], att[qi][3]));
        float e0 = __expf(att[qi][0] - m);
        float e1 = __expf(att[qi][1] - m);
        float e2 = __expf(att[qi][2] - m);
        float e3 = __expf(att[qi][3] - m);
        float inv = 1.0f / (e0 + e1 + e2 + e3);
        att[qi][0] = e0 * inv; att[qi][1] = e1 * inv;
        att[qi][2] = e2 * inv; att[qi][3] = e3 * inv;
    }
    // o = att @ v (this thread's columns)
    float o[4][4];
#pragma unroll
    for (int qi = 0; qi < 4; qi++)
#pragma unroll
        for (int c = 0; c < 4; c++)
            o[qi][c] = att[qi][0] * v[0][c] + att[qi][1] * v[1][c] +
                       att[qi][2] * v[2][c] + att[qi][3] * v[3][c];

    __syncwarp();
#pragma unroll
    for (int s = 0; s < 4; s++)
        *(float4*)(xrow + s * 64 + j0) = make_float4(o[s][0], o[s][1], o[s][2], o[s][3]);
    __syncwarp();

    // output projection: out = o @ Wo
    float out[4][4];
#pragma unroll
    for (int s = 0; s < 4; s++)
#pragma unroll
        for (int c = 0; c < 4; c++) out[s][c] = 0.f;

#pragma unroll 4
    for (int d = 0; d < 64; d++) {
        float4 wo = *(const float4*)(sWo + d * 64 + j0);
#pragma unroll
        for (int s = 0; s < 4; s++) {
            float ov = xrow[s * 64 + d];
            out[s][0] += ov * wo.x; out[s][1] += ov * wo.y;
            out[s][2] += ov * wo.z; out[s][3] += ov * wo.w;
        }
    }

    // epilogue with residuals
    size_t base = (size_t)(nodeBase + nl) * NODE_F;
#pragma unroll
    for (int s = 0; s < 4; s++) {
        float4 r = make_float4(out[s][0], out[s][1], out[s][2], out[s][3]);
        float4* hp = (float4*)(g_h + base + s * 64 + j0);
        if (RES) {
            float4 hold = *hp;
            float4 av = *(const float4*)(g_agg + base + s * 64 + j0);
            r.x += hold.x + av.x; r.y += hold.y + av.y;
            r.z += hold.z + av.z; r.w += hold.w + av.w;
        }
        *hp = r;
    }
}

// ---------------- final head: score = sum_i pooled_i @ W_pred[i] + b_pred[i] ----------------
__global__ void score_kernel(const float* __restrict__ Wp,
                             const float* __restrict__ bp,
                             float* __restrict__ out) {
    int g = blockIdx.x;          // 128 graphs
    int t = threadIdx.x;         // 64 threads: (s, o)
    int s = t >> 4, o = t & 15;
    float acc = 0.0f;
#pragma unroll
    for (int i = 0; i < 4; i++) {
        acc += __ldg(bp + i * 16 + o);
        const float* p = g_pooled + (size_t)i * (N_GRAPHS * NODE_F) + g * NODE_F + s * 64;
        const float* wp = Wp + i * 1024 + o;
        float a2 = 0.0f;
#pragma unroll 8
        for (int d = 0; d < 64; d++) a2 += p[d] * __ldg(wp + d * 16);
        acc += a2;
    }
    out[g * 64 + s * 16 + o] = acc;
}

// ---------------- launch ----------------
extern "C" void kernel_launch(void* const* d_in, const int* in_sizes, int n_in,
                              void* d_out, int out_size) {
    const float* feat = (const float*)d_in[0];
    const int*   src  = (const int*)d_in[1];
    const int*   dst  = (const int*)d_in[2];
    const int*   gids = (const int*)d_in[3];
    const float* Wq   = (const float*)d_in[4];
    const float* Wk   = (const float*)d_in[5];
    const float* Wv   = (const float*)d_in[6];
    const float* Wo   = (const float*)d_in[7];
    const float* slng = (const float*)d_in[8];
    const float* slnb = (const float*)d_in[9];
    const float* ln1g = (const float*)d_in[10];
    const float* ln1b = (const float*)d_in[11];
    const float* ln2g = (const float*)d_in[12];
    const float* ln2b = (const float*)d_in[13];
    const float* Wp   = (const float*)d_in[14];
    const float* bp   = (const float*)d_in[15];
    float* out = (float*)d_out;

    const int smem = SAB_SMEM_FLOATS * 4;  // 82944 bytes
    cudaFuncSetAttribute(sab_kernel<false>, cudaFuncAttributeMaxDynamicSharedMemorySize, smem);
    cudaFuncSetAttribute(sab_kernel<true>,  cudaFuncAttributeMaxDynamicSharedMemorySize, smem);

    void* hpre_ptr = nullptr;
    cudaGetSymbolAddress(&hpre_ptr, g_hpre);

    // pooled accumulators
    zero_pooled_kernel<<<512, 256>>>();
    // hidden_rep[0] pooling (raw features)
    pool_raw_kernel<<<12500, 256>>>((const float4*)feat, gids);

    // ---- layer 0 ----
    copy_to_agg_kernel<<<12500, 256>>>((const float4*)feat);      // agg = feat
    edge_kernel<<<100000, 256>>>(feat, src, dst);                 // agg += feat[src]
    sab_kernel<false><<<3125, 256, smem>>>(Wq, Wk, Wv, Wo, slng, slnb);
    pool_lnrelu_kernel<<<25000, 256>>>(ln2g, ln2b, gids, 1);

    // ---- layers 1, 2 ----
    for (int i = 1; i <= 2; i++) {
        ln_prep_kernel<<<25000, 256>>>(ln1g + 64 * i, ln1b + 64 * i);     // hpre/agg = LN1(h)
        edge_kernel<<<100000, 256>>>((const float*)hpre_ptr, src, dst);   // agg += hpre[src]
        sab_kernel<true><<<3125, 256, smem>>>(Wq + 4096 * i, Wk + 4096 * i,
                                              Wv + 4096 * i, Wo + 4096 * i,
                                              slng + 64 * i, slnb + 64 * i);
        pool_lnrelu_kernel<<<25000, 256>>>(ln2g + 64 * i, ln2b + 64 * i, gids, i + 1);
    }

    // ---- head ----
    score_kernel<<<N_GRAPHS, 64>>>(Wp, bp, out);
}

// round 5
// speedup vs baseline: 1.4023x; 1.4023x over previous
#include <cuda_runtime.h>
#include <cuda_bf16.h>
#include <cstdint>

#define N_NODES 50000
#define N_EDGES 800000
#define N_GRAPHS 128
#define ROWS (N_NODES * 4)          // 200000 token rows of width 64
#define NODE_F 256                  // floats per node (4 x 64)
#define NB_SCAN 196                 // ceil(50000/256)

// ---------------- scratch (device globals: no allocs allowed) ----------------
__device__ __align__(16) float g_h[N_NODES * NODE_F];     // current hidden state
__device__ __align__(16) float g_agg[N_NODES * NODE_F];   // aggregation buffer
__device__ __align__(16) float g_hpre[N_NODES * NODE_F];  // LN1(h) gather source
__device__ __align__(16) float g_pooled[4 * N_GRAPHS * NODE_F];

// CSR scratch
__device__ int g_deg[N_NODES];
__device__ int g_start[N_NODES];
__device__ int g_cur[N_NODES];
__device__ int g_bsum[256];
__device__ int g_elist[N_EDGES];

// ---------------- vector global reductions (sm_90+) ----------------
__device__ __forceinline__ void red_add_f1(float* addr, float v) {
    asm volatile("red.global.add.f32 [%0], %1;" :: "l"(addr), "f"(v) : "memory");
}

// ---------------- tiny utility kernels ----------------
__global__ void zero_pooled_kernel() {
    int i = blockIdx.x * blockDim.x + threadIdx.x;
    if (i < 4 * N_GRAPHS * NODE_F) g_pooled[i] = 0.0f;
}
__global__ void zero_deg_kernel() {
    int i = blockIdx.x * blockDim.x + threadIdx.x;
    if (i < N_NODES) g_deg[i] = 0;
}

// ---------------- CSR build ----------------
__global__ void hist_kernel(const int* __restrict__ dst) {
    int i = blockIdx.x * blockDim.x + threadIdx.x;
    if (i < N_EDGES) atomicAdd(&g_deg[__ldg(dst + i)], 1);
}

__global__ void scanA_kernel() {
    __shared__ int sm[256];
    int b = blockIdx.x, t = threadIdx.x, i = b * 256 + t;
    int v = (i < N_NODES) ? g_deg[i] : 0;
    sm[t] = v; __syncthreads();
#pragma unroll
    for (int off = 1; off < 256; off <<= 1) {
        int u = (t >= off) ? sm[t - off] : 0;
        __syncthreads();
        sm[t] += u;
        __syncthreads();
    }
    if (i < N_NODES) g_start[i] = sm[t] - v;
    if (t == 255) g_bsum[b] = sm[255];
}

__global__ void scanB_kernel() {
    __shared__ int sm[256];
    int t = threadIdx.x;
    int v = (t < NB_SCAN) ? g_bsum[t] : 0;
    sm[t] = v; __syncthreads();
#pragma unroll
    for (int off = 1; off < 256; off <<= 1) {
        int u = (t >= off) ? sm[t - off] : 0;
        __syncthreads();
        sm[t] += u;
        __syncthreads();
    }
    if (t < NB_SCAN) g_bsum[t] = sm[t] - v;   // exclusive
}

__global__ void scanC_kernel() {
    int i = blockIdx.x * blockDim.x + threadIdx.x;
    if (i < N_NODES) {
        int s = g_start[i] + g_bsum[i >> 8];
        g_start[i] = s;
        g_cur[i] = s;
    }
}

__global__ void fill_kernel(const int* __restrict__ src, const int* __restrict__ dst) {
    int i = blockIdx.x * blockDim.x + threadIdx.x;
    if (i >= N_EDGES) return;
    int d = __ldg(dst + i);
    int pos = atomicAdd(&g_cur[d], 1);
    g_elist[pos] = __ldg(src + i);
}

// ---------------- CSR gather aggregation: agg[n] = hsrc[n] + sum_{e: dst=n} hsrc[src_e]
// one warp per node; each lane owns 2 float4 (8 of 256 floats)
__global__ void agg_kernel(const float* __restrict__ hsrc) {
    int n = (blockIdx.x * blockDim.x + threadIdx.x) >> 5;
    int lane = threadIdx.x & 31;
    if (n >= N_NODES) return;
    int deg = g_deg[n];
    int start = g_start[n];
    const float4* own = (const float4*)hsrc + (size_t)n * 64;
    float4 acc0 = __ldg(own + lane);
    float4 acc1 = __ldg(own + lane + 32);
    int j = 0;
    for (; j + 2 <= deg; j += 2) {
        int s0 = __ldg(g_elist + start + j);
        int s1 = __ldg(g_elist + start + j + 1);
        const float4* p0 = (const float4*)hsrc + (size_t)s0 * 64;
        const float4* p1 = (const float4*)hsrc + (size_t)s1 * 64;
        float4 a0 = __ldg(p0 + lane);
        float4 b0 = __ldg(p0 + lane + 32);
        float4 a1 = __ldg(p1 + lane);
        float4 b1 = __ldg(p1 + lane + 32);
        acc0.x += a0.x + a1.x; acc0.y += a0.y + a1.y;
        acc0.z += a0.z + a1.z; acc0.w += a0.w + a1.w;
        acc1.x += b0.x + b1.x; acc1.y += b0.y + b1.y;
        acc1.z += b0.z + b1.z; acc1.w += b0.w + b1.w;
    }
    if (j < deg) {
        int s0 = __ldg(g_elist + start + j);
        const float4* p0 = (const float4*)hsrc + (size_t)s0 * 64;
        float4 a0 = __ldg(p0 + lane);
        float4 b0 = __ldg(p0 + lane + 32);
        acc0.x += a0.x; acc0.y += a0.y; acc0.z += a0.z; acc0.w += a0.w;
        acc1.x += b0.x; acc1.y += b0.y; acc1.z += b0.z; acc1.w += b0.w;
    }
    float4* pd = (float4*)g_agg + (size_t)n * 64;
    pd[lane] = acc0;
    pd[lane + 32] = acc1;
}

// ---------------- fused pooling (+ optional LN1 prep) ----------------
// Block: 256 threads, 16 nodes (64 rows). Thread t: row = t>>2, quarter q = t&3
// (16 floats). DO_LN: y = LN2(relu(x)); else y = x (raw pooling of feat).
// DO_LN1: also write g_hpre = LN1(x).
// Pool: stage y in smem, block-reduce over the 16 nodes (graph_ids sorted ->
// almost always a single gid per block), emit one set of 256 f32 REDs.
#define XSTRIDE 68

template <bool DO_LN, bool DO_LN1>
__global__ void __launch_bounds__(256)
pool_kernel(const float* __restrict__ srcp,
            const float* __restrict__ g2w, const float* __restrict__ b2w,
            const float* __restrict__ g1w, const float* __restrict__ b1w,
            const int* __restrict__ gids, int layer) {
    __shared__ float X[64 * XSTRIDE];
    __shared__ int sgid[16];

    int t = threadIdx.x;
    int row = t >> 2;          // 0..63 local row
    int q = t & 3;             // quarter (16 floats)
    int grow = blockIdx.x * 64 + row;
    int node = blockIdx.x * 16 + (row >> 2);

    if (t < 16) sgid[t] = __ldg(gids + blockIdx.x * 16 + t);

    // load 16 floats
    float4 xr[4];
    const float4* sp = (const float4*)srcp + (size_t)grow * 16 + q * 4;
#pragma unroll
    for (int i = 0; i < 4; i++) xr[i] = __ldg(sp + i);

    float y[16];
    if (DO_LN) {
        // relu + LN2 stats
        float r[16];
#pragma unroll
        for (int i = 0; i < 4; i++) {
            r[i * 4 + 0] = fmaxf(xr[i].x, 0.f); r[i * 4 + 1] = fmaxf(xr[i].y, 0.f);
            r[i * 4 + 2] = fmaxf(xr[i].z, 0.f); r[i * 4 + 3] = fmaxf(xr[i].w, 0.f);
        }
        float sum = 0.f, sq = 0.f;
#pragma unroll
        for (int i = 0; i < 16; i++) { sum += r[i]; sq += r[i] * r[i]; }
        sum += __shfl_xor_sync(0xFFFFFFFFu, sum, 1);
        sq  += __shfl_xor_sync(0xFFFFFFFFu, sq, 1);
        sum += __shfl_xor_sync(0xFFFFFFFFu, sum, 2);
        sq  += __shfl_xor_sync(0xFFFFFFFFu, sq, 2);
        float mu = sum * (1.0f / 64.0f);
        float rstd = rsqrtf(sq * (1.0f / 64.0f) - mu * mu + 1e-5f);
        int d0 = q * 16;
#pragma unroll
        for (int i = 0; i < 16; i++)
            y[i] = (r[i] - mu) * rstd * __ldg(g2w + d0 + i) + __ldg(b2w + d0 + i);
    } else {
#pragma unroll
        for (int i = 0; i < 4; i++) {
            y[i * 4 + 0] = xr[i].x; y[i * 4 + 1] = xr[i].y;
            y[i * 4 + 2] = xr[i].z; y[i * 4 + 3] = xr[i].w;
        }
    }

    // stage into smem
    float* xs = X + row * XSTRIDE + q * 16;
#pragma unroll
    for (int i = 0; i < 4; i++)
        *(float4*)(xs + i * 4) = make_float4(y[i * 4], y[i * 4 + 1], y[i * 4 + 2], y[i * 4 + 3]);

    if (DO_LN1) {
        // LN1 on raw x
        float sum = 0.f, sq = 0.f;
        float xv[16];
#pragma unroll
        for (int i = 0; i < 4; i++) {
            xv[i * 4 + 0] = xr[i].x; xv[i * 4 + 1] = xr[i].y;
            xv[i * 4 + 2] = xr[i].z; xv[i * 4 + 3] = xr[i].w;
        }
#pragma unroll
        for (int i = 0; i < 16; i++) { sum += xv[i]; sq += xv[i] * xv[i]; }
        sum += __shfl_xor_sync(0xFFFFFFFFu, sum, 1);
        sq  += __shfl_xor_sync(0xFFFFFFFFu, sq, 1);
        sum += __shfl_xor_sync(0xFFFFFFFFu, sum, 2);
        sq  += __shfl_xor_sync(0xFFFFFFFFu, sq, 2);
        float mu = sum * (1.0f / 64.0f);
        float rstd = rsqrtf(sq * (1.0f / 64.0f) - mu * mu + 1e-5f);
        int d0 = q * 16;
        float4 o[4];
#pragma unroll
        for (int i = 0; i < 4; i++) {
            o[i].x = (xv[i * 4 + 0] - mu) * rstd * __ldg(g1w + d0 + i * 4 + 0) + __ldg(b1w + d0 + i * 4 + 0);
            o[i].y = (xv[i * 4 + 1] - mu) * rstd * __ldg(g1w + d0 + i * 4 + 1) + __ldg(b1w + d0 + i * 4 + 1);
            o[i].z = (xv[i * 4 + 2] - mu) * rstd * __ldg(g1w + d0 + i * 4 + 2) + __ldg(b1w + d0 + i * 4 + 2);
            o[i].w = (xv[i * 4 + 3] - mu) * rstd * __ldg(g1w + d0 + i * 4 + 3) + __ldg(b1w + d0 + i * 4 + 3);
        }
        float4* hp = (float4*)g_hpre + (size_t)grow * 16 + q * 4;
#pragma unroll
        for (int i = 0; i < 4; i++) hp[i] = o[i];
    }

    __syncthreads();

    // block reduce over 16 nodes -> pooled
    int s = t >> 6;         // 0..3
    int d = t & 63;
    float* poolBase = g_pooled + (size_t)layer * (N_GRAPHS * NODE_F);
    if (sgid[0] == sgid[15]) {
        float acc = 0.f;
#pragma unroll
        for (int n = 0; n < 16; n++) acc += X[(n * 4 + s) * XSTRIDE + d];
        red_add_f1(poolBase + sgid[0] * NODE_F + s * 64 + d, acc);
    } else {
#pragma unroll 4
        for (int n = 0; n < 16; n++) {
            float v = X[(n * 4 + s) * XSTRIDE + d];
            red_add_f1(poolBase + sgid[n] * NODE_F + s * 64 + d, v);
        }
    }
}

// ---------------- fused SAB block ----------------
#define SAB_SMEM_FLOATS (4 * 4096 + 128 + 16 * 264)

template <bool RES>
__global__ void __launch_bounds__(256)
sab_kernel(const float* __restrict__ Wq, const float* __restrict__ Wk,
           const float* __restrict__ Wv, const float* __restrict__ Wo,
           const float* __restrict__ lng, const float* __restrict__ lnb) {
    extern __shared__ float sm[];
    float* sWq = sm;
    float* sWk = sm + 4096;
    float* sWv = sm + 8192;
    float* sWo = sm + 12288;
    float* sLg = sm + 16384;
    float* sLb = sm + 16448;
    float* sX  = sm + 16512;   // 16 nodes, stride 264 floats (bank-skewed)

    int tid = threadIdx.x;
    int nodeBase = blockIdx.x * 16;

    {
        float4* d4 = (float4*)sWq;
#pragma unroll
        for (int i = tid; i < 1024; i += 256) {
            d4[i]        = __ldg((const float4*)Wq + i);
            d4[1024 + i] = __ldg((const float4*)Wk + i);
            d4[2048 + i] = __ldg((const float4*)Wv + i);
            d4[3072 + i] = __ldg((const float4*)Wo + i);
        }
        if (tid < 64) {
            sLg[tid] = __ldg(lng + tid);
            sLb[tid] = __ldg(lnb + tid);
        }
    }
    {
        const float4* srcp = (const float4*)g_agg + (size_t)nodeBase * 64;
        float4* sx4 = (float4*)sX;
#pragma unroll
        for (int i = tid; i < 1024; i += 256) {
            int n = i >> 6, r = i & 63;
            sx4[n * 66 + r] = __ldg(srcp + i);
        }
    }
    __syncthreads();

    int nl = tid >> 4;
    int t  = tid & 15;
    float* xrow = sX + nl * 264;

    {
        int s = t & 3, qq = t >> 2;
        float sum = 0.f, sq = 0.f;
#pragma unroll
        for (int c = 0; c < 16; c++) {
            float xv = xrow[s * 64 + qq * 16 + c];
            sum += xv; sq += xv * xv;
        }
        sum += __shfl_xor_sync(0xFFFFFFFFu, sum, 4);
        sq  += __shfl_xor_sync(0xFFFFFFFFu, sq, 4);
        sum += __shfl_xor_sync(0xFFFFFFFFu, sum, 8);
        sq  += __shfl_xor_sync(0xFFFFFFFFu, sq, 8);
        float mu = sum * (1.0f / 64.0f);
        float rstd = rsqrtf(sq * (1.0f / 64.0f) - mu * mu + 1e-5f);
#pragma unroll
        for (int c = 0; c < 16; c++) {
            int d = qq * 16 + c;
            float xv = xrow[s * 64 + d];
            xrow[s * 64 + d] = (xv - mu) * rstd * sLg[d] + sLb[d];
        }
    }
    __syncwarp();

    int j0 = t * 4;
    float q[4][4], k[4][4], v[4][4];
#pragma unroll
    for (int s = 0; s < 4; s++)
#pragma unroll
        for (int c = 0; c < 4; c++) { q[s][c] = 0.f; k[s][c] = 0.f; v[s][c] = 0.f; }

#pragma unroll 4
    for (int d = 0; d < 64; d++) {
        float4 wq = *(const float4*)(sWq + d * 64 + j0);
        float4 wk = *(const float4*)(sWk + d * 64 + j0);
        float4 wv = *(const float4*)(sWv + d * 64 + j0);
#pragma unroll
        for (int s = 0; s < 4; s++) {
            float xv = xrow[s * 64 + d];
            q[s][0] += xv * wq.x; q[s][1] += xv * wq.y; q[s][2] += xv * wq.z; q[s][3] += xv * wq.w;
            k[s][0] += xv * wk.x; k[s][1] += xv * wk.y; k[s][2] += xv * wk.z; k[s][3] += xv * wk.w;
            v[s][0] += xv * wv.x; v[s][1] += xv * wv.y; v[s][2] += xv * wv.z; v[s][3] += xv * wv.w;
        }
    }
#pragma unroll
    for (int s = 0; s < 4; s++)
#pragma unroll
        for (int c = 0; c < 4; c++) q[s][c] *= 0.25f;

    float att[4][4];
#pragma unroll
    for (int qi = 0; qi < 4; qi++)
#pragma unroll
        for (int si = 0; si < 4; si++) {
            float p = q[qi][0] * k[si][0] + q[qi][1] * k[si][1] +
                      q[qi][2] * k[si][2] + q[qi][3] * k[si][3];
            p += __shfl_xor_sync(0xFFFFFFFFu, p, 1);
            p += __shfl_xor_sync(0xFFFFFFFFu, p, 2);
            att[qi][si] = p;
        }
#pragma unroll
    for (int qi = 0; qi < 4; qi++) {
        float m = fmaxf(fmaxf(att[qi][0], att[qi][1]), fmaxf(att[qi][2], att[qi][3]));
        float e0 = __expf(att[qi][0] - m);
        float e1 = __expf(att[qi][1] - m);
        float e2 = __expf(att[qi][2] - m);
        float e3 = __expf(att[qi][3] - m);
        float inv = 1.0f / (e0 + e1 + e2 + e3);
        att[qi][0] = e0 * inv; att[qi][1] = e1 * inv;
        att[qi][2] = e2 * inv; att[qi][3] = e3 * inv;
    }
    float o[4][4];
#pragma unroll
    for (int qi = 0; qi < 4; qi++)
#pragma unroll
        for (int c = 0; c < 4; c++)
            o[qi][c] = att[qi][0] * v[0][c] + att[qi][1] * v[1][c] +
                       att[qi][2] * v[2][c] + att[qi][3] * v[3][c];

    __syncwarp();
#pragma unroll
    for (int s = 0; s < 4; s++)
        *(float4*)(xrow + s * 64 + j0) = make_float4(o[s][0], o[s][1], o[s][2], o[s][3]);
    __syncwarp();

    float out[4][4];
#pragma unroll
    for (int s = 0; s < 4; s++)
#pragma unroll
        for (int c = 0; c < 4; c++) out[s][c] = 0.f;

#pragma unroll 4
    for (int d = 0; d < 64; d++) {
        float4 wo = *(const float4*)(sWo + d * 64 + j0);
#pragma unroll
        for (int s = 0; s < 4; s++) {
            float ov = xrow[s * 64 + d];
            out[s][0] += ov * wo.x; out[s][1] += ov * wo.y;
            out[s][2] += ov * wo.z; out[s][3] += ov * wo.w;
        }
    }

    size_t base = (size_t)(nodeBase + nl) * NODE_F;
#pragma unroll
    for (int s = 0; s < 4; s++) {
        float4 r = make_float4(out[s][0], out[s][1], out[s][2], out[s][3]);
        float4* hp = (float4*)(g_h + base + s * 64 + j0);
        if (RES) {
            float4 hold = *hp;
            float4 av = *(const float4*)(g_agg + base + s * 64 + j0);
            r.x += hold.x + av.x; r.y += hold.y + av.y;
            r.z += hold.z + av.z; r.w += hold.w + av.w;
        }
        *hp = r;
    }
}

// ---------------- final head ----------------
__global__ void score_kernel(const float* __restrict__ Wp,
                             const float* __restrict__ bp,
                             float* __restrict__ out) {
    int g = blockIdx.x;
    int t = threadIdx.x;
    int s = t >> 4, o = t & 15;
    float acc = 0.0f;
#pragma unroll
    for (int i = 0; i < 4; i++) {
        acc += __ldg(bp + i * 16 + o);
        const float* p = g_pooled + (size_t)i * (N_GRAPHS * NODE_F) + g * NODE_F + s * 64;
        const float* wp = Wp + i * 1024 + o;
        float a2 = 0.0f;
#pragma unroll 8
        for (int d = 0; d < 64; d++) a2 += p[d] * __ldg(wp + d * 16);
        acc += a2;
    }
    out[g * 64 + s * 16 + o] = acc;
}

// ---------------- launch ----------------
extern "C" void kernel_launch(void* const* d_in, const int* in_sizes, int n_in,
                              void* d_out, int out_size) {
    const float* feat = (const float*)d_in[0];
    const int*   src  = (const int*)d_in[1];
    const int*   dst  = (const int*)d_in[2];
    const int*   gids = (const int*)d_in[3];
    const float* Wq   = (const float*)d_in[4];
    const float* Wk   = (const float*)d_in[5];
    const float* Wv   = (const float*)d_in[6];
    const float* Wo   = (const float*)d_in[7];
    const float* slng = (const float*)d_in[8];
    const float* slnb = (const float*)d_in[9];
    const float* ln1g = (const float*)d_in[10];
    const float* ln1b = (const float*)d_in[11];
    const float* ln2g = (const float*)d_in[12];
    const float* ln2b = (const float*)d_in[13];
    const float* Wp   = (const float*)d_in[14];
    const float* bp   = (const float*)d_in[15];
    float* out = (float*)d_out;

    const int smem = SAB_SMEM_FLOATS * 4;  // 82944 bytes
    cudaFuncSetAttribute(sab_kernel<false>, cudaFuncAttributeMaxDynamicSharedMemorySize, smem);
    cudaFuncSetAttribute(sab_kernel<true>,  cudaFuncAttributeMaxDynamicSharedMemorySize, smem);

    void* hpre_ptr = nullptr;
    cudaGetSymbolAddress(&hpre_ptr, g_hpre);
    void* h_ptr = nullptr;
    cudaGetSymbolAddress(&h_ptr, g_h);

    // ---- CSR build (once per launch, reused by all 3 layers) ----
    zero_deg_kernel<<<NB_SCAN, 256>>>();
    zero_pooled_kernel<<<512, 256>>>();
    hist_kernel<<<3125, 256>>>(dst);
    scanA_kernel<<<NB_SCAN, 256>>>();
    scanB_kernel<<<1, 256>>>();
    scanC_kernel<<<NB_SCAN, 256>>>();
    fill_kernel<<<3125, 256>>>(src, dst);

    // hidden_rep[0]: raw feature pooling
    pool_kernel<false, false><<<3125, 256>>>(feat, nullptr, nullptr, nullptr, nullptr, gids, 0);

    // ---- layer 0 ----
    agg_kernel<<<6250, 256>>>(feat);                          // agg = feat + msg(feat)
    sab_kernel<false><<<3125, 256, smem>>>(Wq, Wk, Wv, Wo, slng, slnb);
    // pool hidden_rep[1] (ln2[0]) + LN1 prep for layer 1 (ln1[1])
    pool_kernel<true, true><<<3125, 256>>>((const float*)h_ptr, ln2g, ln2b,
                                           ln1g + 64, ln1b + 64, gids, 1);

    // ---- layer 1 ----
    agg_kernel<<<6250, 256>>>((const float*)hpre_ptr);
    sab_kernel<true><<<3125, 256, smem>>>(Wq + 4096, Wk + 4096, Wv + 4096, Wo + 4096,
                                          slng + 64, slnb + 64);
    pool_kernel<true, true><<<3125, 256>>>((const float*)h_ptr, ln2g + 64, ln2b + 64,
                                           ln1g + 128, ln1b + 128, gids, 2);

    // ---- layer 2 ----
    agg_kernel<<<6250, 256>>>((const float*)hpre_ptr);
    sab_kernel<true><<<3125, 256, smem>>>(Wq + 8192, Wk + 8192, Wv + 8192, Wo + 8192,
                                          slng + 128, slnb + 128);
    pool_kernel<true, false><<<3125, 256>>>((const float*)h_ptr, ln2g + 128, ln2b + 128,
                                            nullptr, nullptr, gids, 3);

    // ---- head ----
    score_kernel<<<N_GRAPHS, 64>>>(Wp, bp, out);
}

// round 6
// speedup vs baseline: 1.4357x; 1.0238x over previous
#include <cuda_runtime.h>
#include <cuda_bf16.h>
#include <cstdint>

#define N_NODES 50000
#define N_EDGES 800000
#define N_GRAPHS 128
#define ROWS (N_NODES * 4)          // 200000 token rows of width 64
#define NODE_F 256                  // floats per node (4 x 64)
#define NB_SCAN 196                 // ceil(50000/256)

// ---------------- scratch (device globals: no allocs allowed) ----------------
__device__ __align__(16) float g_h[N_NODES * NODE_F];     // current hidden state
__device__ __align__(16) float g_agg[N_NODES * NODE_F];   // aggregation buffer
__device__ __align__(16) float g_hpre[N_NODES * NODE_F];  // LN1(h) gather source
__device__ __align__(16) float g_pooled[4 * N_GRAPHS * NODE_F];

// CSR scratch
__device__ int g_deg[N_NODES];
__device__ int g_start[N_NODES];
__device__ int g_cur[N_NODES];
__device__ int g_bsum[256];
__device__ int g_elist[N_EDGES];

// ---------------- packed fp32 helpers (Blackwell f32x2) ----------------
__device__ __forceinline__ void fma2(unsigned long long& acc,
                                     unsigned long long a, unsigned long long b) {
    asm("fma.rn.f32x2 %0, %1, %2, %0;" : "+l"(acc) : "l"(a), "l"(b));
}
__device__ __forceinline__ float hsum2(unsigned long long a) {
    float lo, hi;
    asm("mov.b64 {%0,%1}, %2;" : "=f"(lo), "=f"(hi) : "l"(a));
    return lo + hi;
}

// ---------------- vector global reductions (sm_90+) ----------------
__device__ __forceinline__ void red_add_f1(float* addr, float v) {
    asm volatile("red.global.add.f32 [%0], %1;" :: "l"(addr), "f"(v) : "memory");
}

// ---------------- tiny utility kernels ----------------
__global__ void zero_pooled_kernel() {
    int i = blockIdx.x * blockDim.x + threadIdx.x;
    if (i < 4 * N_GRAPHS * NODE_F) g_pooled[i] = 0.0f;
}
__global__ void zero_deg_kernel() {
    int i = blockIdx.x * blockDim.x + threadIdx.x;
    if (i < N_NODES) g_deg[i] = 0;
}

// ---------------- CSR build ----------------
__global__ void hist_kernel(const int* __restrict__ dst) {
    int i = blockIdx.x * blockDim.x + threadIdx.x;
    if (i < N_EDGES) atomicAdd(&g_deg[__ldg(dst + i)], 1);
}

__global__ void scanA_kernel() {
    __shared__ int sm[256];
    int b = blockIdx.x, t = threadIdx.x, i = b * 256 + t;
    int v = (i < N_NODES) ? g_deg[i] : 0;
    sm[t] = v; __syncthreads();
#pragma unroll
    for (int off = 1; off < 256; off <<= 1) {
        int u = (t >= off) ? sm[t - off] : 0;
        __syncthreads();
        sm[t] += u;
        __syncthreads();
    }
    if (i < N_NODES) g_start[i] = sm[t] - v;
    if (t == 255) g_bsum[b] = sm[255];
}

__global__ void scanB_kernel() {
    __shared__ int sm[256];
    int t = threadIdx.x;
    int v = (t < NB_SCAN) ? g_bsum[t] : 0;
    sm[t] = v; __syncthreads();
#pragma unroll
    for (int off = 1; off < 256; off <<= 1) {
        int u = (t >= off) ? sm[t - off] : 0;
        __syncthreads();
        sm[t] += u;
        __syncthreads();
    }
    if (t < NB_SCAN) g_bsum[t] = sm[t] - v;   // exclusive
}

__global__ void scanC_kernel() {
    int i = blockIdx.x * blockDim.x + threadIdx.x;
    if (i < N_NODES) {
        int s = g_start[i] + g_bsum[i >> 8];
        g_start[i] = s;
        g_cur[i] = s;
    }
}

__global__ void fill_kernel(const int* __restrict__ src, const int* __restrict__ dst) {
    int i = blockIdx.x * blockDim.x + threadIdx.x;
    if (i >= N_EDGES) return;
    int d = __ldg(dst + i);
    int pos = atomicAdd(&g_cur[d], 1);
    g_elist[pos] = __ldg(src + i);
}

// ---------------- CSR gather aggregation ----------------
__global__ void agg_kernel(const float* __restrict__ hsrc) {
    int n = (blockIdx.x * blockDim.x + threadIdx.x) >> 5;
    int lane = threadIdx.x & 31;
    if (n >= N_NODES) return;
    int deg = g_deg[n];
    int start = g_start[n];
    const float4* own = (const float4*)hsrc + (size_t)n * 64;
    float4 acc0 = __ldg(own + lane);
    float4 acc1 = __ldg(own + lane + 32);
    int j = 0;
    for (; j + 2 <= deg; j += 2) {
        int s0 = __ldg(g_elist + start + j);
        int s1 = __ldg(g_elist + start + j + 1);
        const float4* p0 = (const float4*)hsrc + (size_t)s0 * 64;
        const float4* p1 = (const float4*)hsrc + (size_t)s1 * 64;
        float4 a0 = __ldg(p0 + lane);
        float4 b0 = __ldg(p0 + lane + 32);
        float4 a1 = __ldg(p1 + lane);
        float4 b1 = __ldg(p1 + lane + 32);
        acc0.x += a0.x + a1.x; acc0.y += a0.y + a1.y;
        acc0.z += a0.z + a1.z; acc0.w += a0.w + a1.w;
        acc1.x += b0.x + b1.x; acc1.y += b0.y + b1.y;
        acc1.z += b0.z + b1.z; acc1.w += b0.w + b1.w;
    }
    if (j < deg) {
        int s0 = __ldg(g_elist + start + j);
        const float4* p0 = (const float4*)hsrc + (size_t)s0 * 64;
        float4 a0 = __ldg(p0 + lane);
        float4 b0 = __ldg(p0 + lane + 32);
        acc0.x += a0.x; acc0.y += a0.y; acc0.z += a0.z; acc0.w += a0.w;
        acc1.x += b0.x; acc1.y += b0.y; acc1.z += b0.z; acc1.w += b0.w;
    }
    float4* pd = (float4*)g_agg + (size_t)n * 64;
    pd[lane] = acc0;
    pd[lane + 32] = acc1;
}

// ---------------- fused pooling (+ optional LN1 prep) ----------------
#define XSTRIDE 68

template <bool DO_LN, bool DO_LN1>
__global__ void __launch_bounds__(256)
pool_kernel(const float* __restrict__ srcp,
            const float* __restrict__ g2w, const float* __restrict__ b2w,
            const float* __restrict__ g1w, const float* __restrict__ b1w,
            const int* __restrict__ gids, int layer) {
    __shared__ float X[64 * XSTRIDE];
    __shared__ int sgid[16];

    int t = threadIdx.x;
    int row = t >> 2;          // 0..63 local row
    int q = t & 3;             // quarter (16 floats)
    int grow = blockIdx.x * 64 + row;

    if (t < 16) sgid[t] = __ldg(gids + blockIdx.x * 16 + t);

    float4 xr[4];
    const float4* sp = (const float4*)srcp + (size_t)grow * 16 + q * 4;
#pragma unroll
    for (int i = 0; i < 4; i++) xr[i] = __ldg(sp + i);

    float y[16];
    if (DO_LN) {
        float r[16];
#pragma unroll
        for (int i = 0; i < 4; i++) {
            r[i * 4 + 0] = fmaxf(xr[i].x, 0.f); r[i * 4 + 1] = fmaxf(xr[i].y, 0.f);
            r[i * 4 + 2] = fmaxf(xr[i].z, 0.f); r[i * 4 + 3] = fmaxf(xr[i].w, 0.f);
        }
        float sum = 0.f, sq = 0.f;
#pragma unroll
        for (int i = 0; i < 16; i++) { sum += r[i]; sq += r[i] * r[i]; }
        sum += __shfl_xor_sync(0xFFFFFFFFu, sum, 1);
        sq  += __shfl_xor_sync(0xFFFFFFFFu, sq, 1);
        sum += __shfl_xor_sync(0xFFFFFFFFu, sum, 2);
        sq  += __shfl_xor_sync(0xFFFFFFFFu, sq, 2);
        float mu = sum * (1.0f / 64.0f);
        float rstd = rsqrtf(sq * (1.0f / 64.0f) - mu * mu + 1e-5f);
        int d0 = q * 16;
#pragma unroll
        for (int i = 0; i < 16; i++)
            y[i] = (r[i] - mu) * rstd * __ldg(g2w + d0 + i) + __ldg(b2w + d0 + i);
    } else {
#pragma unroll
        for (int i = 0; i < 4; i++) {
            y[i * 4 + 0] = xr[i].x; y[i * 4 + 1] = xr[i].y;
            y[i * 4 + 2] = xr[i].z; y[i * 4 + 3] = xr[i].w;
        }
    }

    float* xs = X + row * XSTRIDE + q * 16;
#pragma unroll
    for (int i = 0; i < 4; i++)
        *(float4*)(xs + i * 4) = make_float4(y[i * 4], y[i * 4 + 1], y[i * 4 + 2], y[i * 4 + 3]);

    if (DO_LN1) {
        float sum = 0.f, sq = 0.f;
        float xv[16];
#pragma unroll
        for (int i = 0; i < 4; i++) {
            xv[i * 4 + 0] = xr[i].x; xv[i * 4 + 1] = xr[i].y;
            xv[i * 4 + 2] = xr[i].z; xv[i * 4 + 3] = xr[i].w;
        }
#pragma unroll
        for (int i = 0; i < 16; i++) { sum += xv[i]; sq += xv[i] * xv[i]; }
        sum += __shfl_xor_sync(0xFFFFFFFFu, sum, 1);
        sq  += __shfl_xor_sync(0xFFFFFFFFu, sq, 1);
        sum += __shfl_xor_sync(0xFFFFFFFFu, sum, 2);
        sq  += __shfl_xor_sync(0xFFFFFFFFu, sq, 2);
        float mu = sum * (1.0f / 64.0f);
        float rstd = rsqrtf(sq * (1.0f / 64.0f) - mu * mu + 1e-5f);
        int d0 = q * 16;
        float4 o[4];
#pragma unroll
        for (int i = 0; i < 4; i++) {
            o[i].x = (xv[i * 4 + 0] - mu) * rstd * __ldg(g1w + d0 + i * 4 + 0) + __ldg(b1w + d0 + i * 4 + 0);
            o[i].y = (xv[i * 4 + 1] - mu) * rstd * __ldg(g1w + d0 + i * 4 + 1) + __ldg(b1w + d0 + i * 4 + 1);
            o[i].z = (xv[i * 4 + 2] - mu) * rstd * __ldg(g1w + d0 + i * 4 + 2) + __ldg(b1w + d0 + i * 4 + 2);
            o[i].w = (xv[i * 4 + 3] - mu) * rstd * __ldg(g1w + d0 + i * 4 + 3) + __ldg(b1w + d0 + i * 4 + 3);
        }
        float4* hp = (float4*)g_hpre + (size_t)grow * 16 + q * 4;
#pragma unroll
        for (int i = 0; i < 4; i++) hp[i] = o[i];
    }

    __syncthreads();

    int s = t >> 6;
    int d = t & 63;
    float* poolBase = g_pooled + (size_t)layer * (N_GRAPHS * NODE_F);
    if (sgid[0] == sgid[15]) {
        float acc = 0.f;
#pragma unroll
        for (int n = 0; n < 16; n++) acc += X[(n * 4 + s) * XSTRIDE + d];
        red_add_f1(poolBase + sgid[0] * NODE_F + s * 64 + d, acc);
    } else {
#pragma unroll 4
        for (int n = 0; n < 16; n++) {
            float v = X[(n * 4 + s) * XSTRIDE + d];
            red_add_f1(poolBase + sgid[n] * NODE_F + s * 64 + d, v);
        }
    }
}

// ---------------- fused SAB block (f32x2 packed-FMA version) ----------------
// Weights staged TRANSPOSED: sWt[c][d] with stride 68 and XOR swizzle on d
// (d ^ (((c>>3)&7)<<2)) so the 16 lanes of a node hit 16 distinct bank
// segments on each LDS.128 w-quad load. Reduction dim d packed pairwise into
// fma.rn.f32x2 (full fp32).
#define WT_STRIDE 68
#define SW_Q 0
#define SW_K (64 * WT_STRIDE)
#define SW_V (2 * 64 * WT_STRIDE)
#define SW_O (3 * 64 * WT_STRIDE)
#define SW_LG (4 * 64 * WT_STRIDE)
#define SW_LB (SW_LG + 64)
#define SW_X  (SW_LB + 64)
#define SAB_SMEM_FLOATS (SW_X + 16 * 264)

template <bool RES>
__global__ void __launch_bounds__(256, 2)
sab_kernel(const float* __restrict__ Wq, const float* __restrict__ Wk,
           const float* __restrict__ Wv, const float* __restrict__ Wo,
           const float* __restrict__ lng, const float* __restrict__ lnb) {
    extern __shared__ float sm[];
    float* sX = sm + SW_X;   // 16 nodes, stride 264 floats

    int tid = threadIdx.x;
    int nodeBase = blockIdx.x * 16;

    // ---- stage weights transposed+swizzled ----
    {
        const float4* W4[4] = {(const float4*)Wq, (const float4*)Wk,
                               (const float4*)Wv, (const float4*)Wo};
        float* base[4] = {sm + SW_Q, sm + SW_K, sm + SW_V, sm + SW_O};
#pragma unroll
        for (int m = 0; m < 4; m++) {
            float* dstp = base[m];
            const float4* srcp = W4[m];
#pragma unroll
            for (int i = tid; i < 1024; i += 256) {
                int d = i >> 4, c0 = (i & 15) << 2;
                float4 w = __ldg(srcp + i);
                int ds = d ^ (((c0 >> 3) & 7) << 2);
                dstp[(c0 + 0) * WT_STRIDE + ds] = w.x;
                dstp[(c0 + 1) * WT_STRIDE + ds] = w.y;
                dstp[(c0 + 2) * WT_STRIDE + ds] = w.z;
                dstp[(c0 + 3) * WT_STRIDE + ds] = w.w;
            }
        }
        if (tid < 64) {
            sm[SW_LG + tid] = __ldg(lng + tid);
            sm[SW_LB + tid] = __ldg(lnb + tid);
        }
    }
    // ---- stage x tile ----
    {
        const float4* srcp = (const float4*)g_agg + (size_t)nodeBase * 64;
        float4* sx4 = (float4*)sX;
#pragma unroll
        for (int i = tid; i < 1024; i += 256) {
            int n = i >> 6, r = i & 63;
            sx4[n * 66 + r] = __ldg(srcp + i);
        }
    }
    __syncthreads();

    int nl = tid >> 4;
    int t  = tid & 15;
    float* xrow = sX + nl * 264;

    // ---- LayerNorm (in place) ----
    {
        int s = t & 3, qq = t >> 2;
        float sum = 0.f, sq = 0.f;
#pragma unroll
        for (int c = 0; c < 16; c++) {
            float xv = xrow[s * 64 + qq * 16 + c];
            sum += xv; sq += xv * xv;
        }
        sum += __shfl_xor_sync(0xFFFFFFFFu, sum, 4);
        sq  += __shfl_xor_sync(0xFFFFFFFFu, sq, 4);
        sum += __shfl_xor_sync(0xFFFFFFFFu, sum, 8);
        sq  += __shfl_xor_sync(0xFFFFFFFFu, sq, 8);
        float mu = sum * (1.0f / 64.0f);
        float rstd = rsqrtf(sq * (1.0f / 64.0f) - mu * mu + 1e-5f);
#pragma unroll
        for (int c = 0; c < 16; c++) {
            int d = qq * 16 + c;
            float xv = xrow[s * 64 + d];
            xrow[s * 64 + d] = (xv - mu) * rstd * sm[SW_LG + d] + sm[SW_LB + d];
        }
    }
    __syncwarp();

    int j0 = t * 4;
    int fsw = ((j0 >> 3) & 7) << 2;          // swizzle, constant over cc (j0%8 in {0,4})
    int wbase = j0 * WT_STRIDE;              // c = j0 row base

    // ---- Phase A: q,k projections (packed over d) ----
    unsigned long long accq[4][4], acck[4][4];
#pragma unroll
    for (int s = 0; s < 4; s++)
#pragma unroll
        for (int c = 0; c < 4; c++) { accq[s][c] = 0ull; acck[s][c] = 0ull; }

#pragma unroll 4
    for (int dq = 0; dq < 64; dq += 4) {
        ulonglong2 xq[4];
#pragma unroll
        for (int s = 0; s < 4; s++)
            xq[s] = *(const ulonglong2*)(xrow + s * 64 + dq);
        int dsw = dq ^ fsw;
#pragma unroll
        for (int cc = 0; cc < 4; cc++) {
            int wi = wbase + cc * WT_STRIDE + dsw;
            ulonglong2 wq = *(const ulonglong2*)(sm + SW_Q + wi);
            ulonglong2 wk = *(const ulonglong2*)(sm + SW_K + wi);
#pragma unroll
            for (int s = 0; s < 4; s++) {
                fma2(accq[s][cc], xq[s].x, wq.x);
                fma2(accq[s][cc], xq[s].y, wq.y);
                fma2(acck[s][cc], xq[s].x, wk.x);
                fma2(acck[s][cc], xq[s].y, wk.y);
            }
        }
    }

    float q[4][4], k[4][4];
#pragma unroll
    for (int s = 0; s < 4; s++)
#pragma unroll
        for (int c = 0; c < 4; c++) {
            q[s][c] = hsum2(accq[s][c]) * 0.25f;   // 1/sqrt(dk)
            k[s][c] = hsum2(acck[s][c]);
        }

    // ---- attention scores + softmax ----
    float att[4][4];
#pragma unroll
    for (int qi = 0; qi < 4; qi++)
#pragma unroll
        for (int si = 0; si < 4; si++) {
            float p = q[qi][0] * k[si][0] + q[qi][1] * k[si][1] +
                      q[qi][2] * k[si][2] + q[qi][3] * k[si][3];
            p += __shfl_xor_sync(0xFFFFFFFFu, p, 1);
            p += __shfl_xor_sync(0xFFFFFFFFu, p, 2);
            att[qi][si] = p;
        }
#pragma unroll
    for (int qi = 0; qi < 4; qi++) {
        float m = fmaxf(fmaxf(att[qi][0], att[qi][1]), fmaxf(att[qi][2], att[qi][3]));
        float e0 = __expf(att[qi][0] - m);
        float e1 = __expf(att[qi][1] - m);
        float e2 = __expf(att[qi][2] - m);
        float e3 = __expf(att[qi][3] - m);
        float inv = 1.0f / (e0 + e1 + e2 + e3);
        att[qi][0] = e0 * inv; att[qi][1] = e1 * inv;
        att[qi][2] = e2 * inv; att[qi][3] = e3 * inv;
    }

    // ---- Phase B: v projection (packed over d) ----
    unsigned long long accv[4][4];
#pragma unroll
    for (int s = 0; s < 4; s++)
#pragma unroll
        for (int c = 0; c < 4; c++) accv[s][c] = 0ull;

#pragma unroll 4
    for (int dq = 0; dq < 64; dq += 4) {
        ulonglong2 xq[4];
#pragma unroll
        for (int s = 0; s < 4; s++)
            xq[s] = *(const ulonglong2*)(xrow + s * 64 + dq);
        int dsw = dq ^ fsw;
#pragma unroll
        for (int cc = 0; cc < 4; cc++) {
            ulonglong2 wv = *(const ulonglong2*)(sm + SW_V + wbase + cc * WT_STRIDE + dsw);
#pragma unroll
            for (int s = 0; s < 4; s++) {
                fma2(accv[s][cc], xq[s].x, wv.x);
                fma2(accv[s][cc], xq[s].y, wv.y);
            }
        }
    }
    float v[4][4];
#pragma unroll
    for (int s = 0; s < 4; s++)
#pragma unroll
        for (int c = 0; c < 4; c++) v[s][c] = hsum2(accv[s][c]);

    // o = att @ v
    float o[4][4];
#pragma unroll
    for (int qi = 0; qi < 4; qi++)
#pragma unroll
        for (int c = 0; c < 4; c++)
            o[qi][c] = att[qi][0] * v[0][c] + att[qi][1] * v[1][c] +
                       att[qi][2] * v[2][c] + att[qi][3] * v[3][c];

    __syncwarp();
#pragma unroll
    for (int s = 0; s < 4; s++)
        *(float4*)(xrow + s * 64 + j0) = make_float4(o[s][0], o[s][1], o[s][2], o[s][3]);
    __syncwarp();

    // ---- Phase C: output projection o @ Wo (packed over d) ----
    unsigned long long acco[4][4];
#pragma unroll
    for (int s = 0; s < 4; s++)
#pragma unroll
        for (int c = 0; c < 4; c++) acco[s][c] = 0ull;

#pragma unroll 4
    for (int dq = 0; dq < 64; dq += 4) {
        ulonglong2 xq[4];
#pragma unroll
        for (int s = 0; s < 4; s++)
            xq[s] = *(const ulonglong2*)(xrow + s * 64 + dq);
        int dsw = dq ^ fsw;
#pragma unroll
        for (int cc = 0; cc < 4; cc++) {
            ulonglong2 wo = *(const ulonglong2*)(sm + SW_O + wbase + cc * WT_STRIDE + dsw);
#pragma unroll
            for (int s = 0; s < 4; s++) {
                fma2(acco[s][cc], xq[s].x, wo.x);
                fma2(acco[s][cc], xq[s].y, wo.y);
            }
        }
    }

    // ---- epilogue with residuals ----
    size_t base = (size_t)(nodeBase + nl) * NODE_F;
#pragma unroll
    for (int s = 0; s < 4; s++) {
        float4 r = make_float4(hsum2(acco[s][0]), hsum2(acco[s][1]),
                               hsum2(acco[s][2]), hsum2(acco[s][3]));
        float4* hp = (float4*)(g_h + base + s * 64 + j0);
        if (RES) {
            float4 hold = *hp;
            float4 av = *(const float4*)(g_agg + base + s * 64 + j0);
            r.x += hold.x + av.x; r.y += hold.y + av.y;
            r.z += hold.z + av.z; r.w += hold.w + av.w;
        }
        *hp = r;
    }
}

// ---------------- final head ----------------
__global__ void score_kernel(const float* __restrict__ Wp,
                             const float* __restrict__ bp,
                             float* __restrict__ out) {
    int g = blockIdx.x;
    int t = threadIdx.x;
    int s = t >> 4, o = t & 15;
    float acc = 0.0f;
#pragma unroll
    for (int i = 0; i < 4; i++) {
        acc += __ldg(bp + i * 16 + o);
        const float* p = g_pooled + (size_t)i * (N_GRAPHS * NODE_F) + g * NODE_F + s * 64;
        const float* wp = Wp + i * 1024 + o;
        float a2 = 0.0f;
#pragma unroll 8
        for (int d = 0; d < 64; d++) a2 += p[d] * __ldg(wp + d * 16);
        acc += a2;
    }
    out[g * 64 + s * 16 + o] = acc;
}

// ---------------- launch ----------------
extern "C" void kernel_launch(void* const* d_in, const int* in_sizes, int n_in,
                              void* d_out, int out_size) {
    const float* feat = (const float*)d_in[0];
    const int*   src  = (const int*)d_in[1];
    const int*   dst  = (const int*)d_in[2];
    const int*   gids = (const int*)d_in[3];
    const float* Wq   = (const float*)d_in[4];
    const float* Wk   = (const float*)d_in[5];
    const float* Wv   = (const float*)d_in[6];
    const float* Wo   = (const float*)d_in[7];
    const float* slng = (const float*)d_in[8];
    const float* slnb = (const float*)d_in[9];
    const float* ln1g = (const float*)d_in[10];
    const float* ln1b = (const float*)d_in[11];
    const float* ln2g = (const float*)d_in[12];
    const float* ln2b = (const float*)d_in[13];
    const float* Wp   = (const float*)d_in[14];
    const float* bp   = (const float*)d_in[15];
    float* out = (float*)d_out;

    const int smem = SAB_SMEM_FLOATS * 4;   // ~87 KB -> 2 CTAs/SM
    cudaFuncSetAttribute(sab_kernel<false>, cudaFuncAttributeMaxDynamicSharedMemorySize, smem);
    cudaFuncSetAttribute(sab_kernel<true>,  cudaFuncAttributeMaxDynamicSharedMemorySize, smem);

    void* hpre_ptr = nullptr;
    cudaGetSymbolAddress(&hpre_ptr, g_hpre);
    void* h_ptr = nullptr;
    cudaGetSymbolAddress(&h_ptr, g_h);

    // ---- CSR build (once per launch, reused by all 3 layers) ----
    zero_deg_kernel<<<NB_SCAN, 256>>>();
    zero_pooled_kernel<<<512, 256>>>();
    hist_kernel<<<3125, 256>>>(dst);
    scanA_kernel<<<NB_SCAN, 256>>>();
    scanB_kernel<<<1, 256>>>();
    scanC_kernel<<<NB_SCAN, 256>>>();
    fill_kernel<<<3125, 256>>>(src, dst);

    // hidden_rep[0]: raw feature pooling
    pool_kernel<false, false><<<3125, 256>>>(feat, nullptr, nullptr, nullptr, nullptr, gids, 0);

    // ---- layer 0 ----
    agg_kernel<<<6250, 256>>>(feat);
    sab_kernel<false><<<3125, 256, smem>>>(Wq, Wk, Wv, Wo, slng, slnb);
    pool_kernel<true, true><<<3125, 256>>>((const float*)h_ptr, ln2g, ln2b,
                                           ln1g + 64, ln1b + 64, gids, 1);

    // ---- layer 1 ----
    agg_kernel<<<6250, 256>>>((const float*)hpre_ptr);
    sab_kernel<true><<<3125, 256, smem>>>(Wq + 4096, Wk + 4096, Wv + 4096, Wo + 4096,
                                          slng + 64, slnb + 64);
    pool_kernel<true, true><<<3125, 256>>>((const float*)h_ptr, ln2g + 64, ln2b + 64,
                                           ln1g + 128, ln1b + 128, gids, 2);

    // ---- layer 2 ----
    agg_kernel<<<6250, 256>>>((const float*)hpre_ptr);
    sab_kernel<true><<<3125, 256, smem>>>(Wq + 8192, Wk + 8192, Wv + 8192, Wo + 8192,
                                          slng + 128, slnb + 128);
    pool_kernel<true, false><<<3125, 256>>>((const float*)h_ptr, ln2g + 128, ln2b + 128,
                                            nullptr, nullptr, gids, 3);

    // ---- head ----
    score_kernel<<<N_GRAPHS, 64>>>(Wp, bp, out);
}

// round 9
// speedup vs baseline: 1.5542x; 1.0826x over previous
#include <cuda_runtime.h>
#include <cuda_bf16.h>
#include <cstdint>

#define N_NODES 50000
#define N_EDGES 800000
#define N_GRAPHS 128
#define ROWS (N_NODES * 4)
#define NODE_F 256
#define NB_SCAN 196                 // ceil(50000/256)

// ---------------- scratch (device globals) ----------------
__device__ __align__(16) float g_h[N_NODES * NODE_F];
__device__ __align__(16) float g_hpreA[N_NODES * NODE_F];   // ping
__device__ __align__(16) float g_hpreB[N_NODES * NODE_F];   // pong
__device__ __align__(16) float g_pooled[4 * N_GRAPHS * NODE_F];

__device__ int g_deg[N_NODES];
__device__ int g_start[N_NODES];
__device__ int g_cur[N_NODES];
__device__ int g_bsum[256];
__device__ int g_elist[N_EDGES];

// ---------------- packed fp32 helpers ----------------
__device__ __forceinline__ void fma2(unsigned long long& acc,
                                     unsigned long long a, unsigned long long b) {
    asm("fma.rn.f32x2 %0, %1, %2, %0;" : "+l"(acc) : "l"(a), "l"(b));
}
__device__ __forceinline__ float hsum2(unsigned long long a) {
    float lo, hi;
    asm("mov.b64 {%0,%1}, %2;" : "=f"(lo), "=f"(hi) : "l"(a));
    return lo + hi;
}
__device__ __forceinline__ void red_add_f1(float* addr, float v) {
    asm volatile("red.global.add.f32 [%0], %1;" :: "l"(addr), "f"(v) : "memory");
}

// ---------------- zeros ----------------
__global__ void zeros_kernel() {
    int i = blockIdx.x * blockDim.x + threadIdx.x;
    if (i < 4 * N_GRAPHS * NODE_F) g_pooled[i] = 0.0f;
    if (i < N_NODES) g_deg[i] = 0;
}

// ---------------- CSR build ----------------
__global__ void hist_kernel(const int* __restrict__ dst) {
    int i = blockIdx.x * blockDim.x + threadIdx.x;
    if (i < N_EDGES) atomicAdd(&g_deg[__ldg(dst + i)], 1);
}

__global__ void scanA_kernel() {
    __shared__ int sm[256];
    int b = blockIdx.x, t = threadIdx.x, i = b * 256 + t;
    int v = (i < N_NODES) ? g_deg[i] : 0;
    sm[t] = v; __syncthreads();
#pragma unroll
    for (int off = 1; off < 256; off <<= 1) {
        int u = (t >= off) ? sm[t - off] : 0;
        __syncthreads();
        sm[t] += u;
        __syncthreads();
    }
    if (i < N_NODES) g_start[i] = sm[t] - v;
    if (t == 255) g_bsum[b] = sm[255];
}

__global__ void scanB_kernel() {
    __shared__ int sm[256];
    int t = threadIdx.x;
    int v = (t < NB_SCAN) ? g_bsum[t] : 0;
    sm[t] = v; __syncthreads();
#pragma unroll
    for (int off = 1; off < 256; off <<= 1) {
        int u = (t >= off) ? sm[t - off] : 0;
        __syncthreads();
        sm[t] += u;
        __syncthreads();
    }
    if (t < NB_SCAN) g_bsum[t] = sm[t] - v;
}

__global__ void scanC_kernel() {
    int i = blockIdx.x * blockDim.x + threadIdx.x;
    if (i < N_NODES) {
        int s = g_start[i] + g_bsum[i >> 8];
        g_start[i] = s;
        g_cur[i] = s;
    }
}

__global__ void fill_kernel(const int* __restrict__ src, const int* __restrict__ dst) {
    int i = blockIdx.x * blockDim.x + threadIdx.x;
    if (i >= N_EDGES) return;
    int d = __ldg(dst + i);
    int pos = atomicAdd(&g_cur[d], 1);
    g_elist[pos] = __ldg(src + i);
}

// ---------------- raw feature pooling (hidden_rep[0]) ----------------
#define XSTRIDE 68
__global__ void __launch_bounds__(256)
pool_raw_kernel(const float* __restrict__ srcp, const int* __restrict__ gids) {
    __shared__ float X[64 * XSTRIDE];
    __shared__ int sgid[16];
    int t = threadIdx.x;
    int row = t >> 2, q = t & 3;
    int grow = blockIdx.x * 64 + row;
    if (t < 16) sgid[t] = __ldg(gids + blockIdx.x * 16 + t);
    float4 xr[4];
    const float4* sp = (const float4*)srcp + (size_t)grow * 16 + q * 4;
#pragma unroll
    for (int i = 0; i < 4; i++) xr[i] = __ldg(sp + i);
    float* xs = X + row * XSTRIDE + q * 16;
#pragma unroll
    for (int i = 0; i < 4; i++) *(float4*)(xs + i * 4) = xr[i];
    __syncthreads();
    int s = t >> 6, d = t & 63;
    if (sgid[0] == sgid[15]) {
        float acc = 0.f;
#pragma unroll
        for (int n = 0; n < 16; n++) acc += X[(n * 4 + s) * XSTRIDE + d];
        red_add_f1(g_pooled + sgid[0] * NODE_F + s * 64 + d, acc);
    } else {
#pragma unroll 4
        for (int n = 0; n < 16; n++)
            red_add_f1(g_pooled + sgid[n] * NODE_F + s * 64 + d,
                       X[(n * 4 + s) * XSTRIDE + d]);
    }
}

// ---------------- fully fused layer kernel ----------------
// gather(hsrc) -> SAB -> h_new -> g_h ; relu+LN2 -> pool RED ; LN1 -> hpre_out
// hpre_out MUST NOT alias hsrc (double-buffered by caller).
#define WT_STRIDE 68
#define SW_Q 0
#define SW_K (64 * WT_STRIDE)
#define SW_V (2 * 64 * WT_STRIDE)
#define SW_O (3 * 64 * WT_STRIDE)
#define SW_LG (4 * 64 * WT_STRIDE)
#define SW_LB (SW_LG + 64)
#define SW_X  (SW_LB + 64)
#define SW_Y  (SW_X + 16 * 264)
#define FUSED_SMEM_FLOATS (SW_Y + 16 * 264)

template <bool RES, bool DO_LN1>
__global__ void __launch_bounds__(256, 2)
fused_layer_kernel(const float* __restrict__ hsrc,
                   float* __restrict__ hpre_out,
                   const float* __restrict__ Wq, const float* __restrict__ Wk,
                   const float* __restrict__ Wv, const float* __restrict__ Wo,
                   const float* __restrict__ lng, const float* __restrict__ lnb,
                   const float* __restrict__ g2w, const float* __restrict__ b2w,
                   const float* __restrict__ g1w, const float* __restrict__ b1w,
                   const int* __restrict__ gids, int layer) {
    extern __shared__ float sm[];
    float* sX = sm + SW_X;      // agg tile (preserved for residual)
    float* sY = sm + SW_Y;      // LN / attention scratch
    __shared__ int sgid[16];

    int tid = threadIdx.x;
    int nodeBase = blockIdx.x * 16;

    if (tid < 16) sgid[tid] = __ldg(gids + nodeBase + tid);

    // ---- stage weights transposed + swizzled ----
    {
        const float4* W4[4] = {(const float4*)Wq, (const float4*)Wk,
                               (const float4*)Wv, (const float4*)Wo};
        float* base[4] = {sm + SW_Q, sm + SW_K, sm + SW_V, sm + SW_O};
#pragma unroll
        for (int m = 0; m < 4; m++) {
            float* dstp = base[m];
            const float4* srcp = W4[m];
#pragma unroll
            for (int i = tid; i < 1024; i += 256) {
                int d = i >> 4, c0 = (i & 15) << 2;
                float4 w = __ldg(srcp + i);
                int ds = d ^ (((c0 >> 3) & 7) << 2);
                dstp[(c0 + 0) * WT_STRIDE + ds] = w.x;
                dstp[(c0 + 1) * WT_STRIDE + ds] = w.y;
                dstp[(c0 + 2) * WT_STRIDE + ds] = w.z;
                dstp[(c0 + 3) * WT_STRIDE + ds] = w.w;
            }
        }
        if (tid < 64) {
            sm[SW_LG + tid] = __ldg(lng + tid);
            sm[SW_LB + tid] = __ldg(lnb + tid);
        }
    }

    // ---- gather aggregation into sX (warp w handles nodes 2w, 2w+1) ----
    {
        int w = tid >> 5, lane = tid & 31;
        float4* sx4 = (float4*)sX;
#pragma unroll
        for (int nn = 0; nn < 2; nn++) {
            int nl = w * 2 + nn;
            int n = nodeBase + nl;
            int deg = g_deg[n];
            int start = g_start[n];
            const float4* own = (const float4*)hsrc + (size_t)n * 64;
            float4 acc0 = __ldg(own + lane);
            float4 acc1 = __ldg(own + lane + 32);
            int j = 0;
            for (; j + 2 <= deg; j += 2) {
                int s0 = __ldg(g_elist + start + j);
                int s1 = __ldg(g_elist + start + j + 1);
                const float4* p0 = (const float4*)hsrc + (size_t)s0 * 64;
                const float4* p1 = (const float4*)hsrc + (size_t)s1 * 64;
                float4 a0 = __ldg(p0 + lane);
                float4 b0 = __ldg(p0 + lane + 32);
                float4 a1 = __ldg(p1 + lane);
                float4 b1 = __ldg(p1 + lane + 32);
                acc0.x += a0.x + a1.x; acc0.y += a0.y + a1.y;
                acc0.z += a0.z + a1.z; acc0.w += a0.w + a1.w;
                acc1.x += b0.x + b1.x; acc1.y += b0.y + b1.y;
                acc1.z += b0.z + b1.z; acc1.w += b0.w + b1.w;
            }
            if (j < deg) {
                int s0 = __ldg(g_elist + start + j);
                const float4* p0 = (const float4*)hsrc + (size_t)s0 * 64;
                float4 a0 = __ldg(p0 + lane);
                float4 b0 = __ldg(p0 + lane + 32);
                acc0.x += a0.x; acc0.y += a0.y; acc0.z += a0.z; acc0.w += a0.w;
                acc1.x += b0.x; acc1.y += b0.y; acc1.z += b0.z; acc1.w += b0.w;
            }
            sx4[nl * 66 + lane] = acc0;
            sx4[nl * 66 + lane + 32] = acc1;
        }
    }
    __syncthreads();

    int nl = tid >> 4;
    int t  = tid & 15;
    float* xin  = sX + nl * 264;   // agg (kept intact)
    float* xrow = sY + nl * 264;   // LN output / attention scratch

    // ---- LayerNorm sX -> sY ----
    {
        int s = t & 3, qq = t >> 2;
        float sum = 0.f, sq = 0.f;
#pragma unroll
        for (int c = 0; c < 16; c++) {
            float xv = xin[s * 64 + qq * 16 + c];
            sum += xv; sq += xv * xv;
        }
        sum += __shfl_xor_sync(0xFFFFFFFFu, sum, 4);
        sq  += __shfl_xor_sync(0xFFFFFFFFu, sq, 4);
        sum += __shfl_xor_sync(0xFFFFFFFFu, sum, 8);
        sq  += __shfl_xor_sync(0xFFFFFFFFu, sq, 8);
        float mu = sum * (1.0f / 64.0f);
        float rstd = rsqrtf(sq * (1.0f / 64.0f) - mu * mu + 1e-5f);
#pragma unroll
        for (int c = 0; c < 16; c++) {
            int d = qq * 16 + c;
            float xv = xin[s * 64 + d];
            xrow[s * 64 + d] = (xv - mu) * rstd * sm[SW_LG + d] + sm[SW_LB + d];
        }
    }
    __syncwarp();

    int j0 = t * 4;
    int fsw = ((j0 >> 3) & 7) << 2;
    int wbase = j0 * WT_STRIDE;

    // ---- Phase A: q,k ----
    unsigned long long accq[4][4], acck[4][4];
#pragma unroll
    for (int s = 0; s < 4; s++)
#pragma unroll
        for (int c = 0; c < 4; c++) { accq[s][c] = 0ull; acck[s][c] = 0ull; }

#pragma unroll 4
    for (int dq = 0; dq < 64; dq += 4) {
        ulonglong2 xq[4];
#pragma unroll
        for (int s = 0; s < 4; s++)
            xq[s] = *(const ulonglong2*)(xrow + s * 64 + dq);
        int dsw = dq ^ fsw;
#pragma unroll
        for (int cc = 0; cc < 4; cc++) {
            int wi = wbase + cc * WT_STRIDE + dsw;
            ulonglong2 wq = *(const ulonglong2*)(sm + SW_Q + wi);
            ulonglong2 wk = *(const ulonglong2*)(sm + SW_K + wi);
#pragma unroll
            for (int s = 0; s < 4; s++) {
                fma2(accq[s][cc], xq[s].x, wq.x);
                fma2(accq[s][cc], xq[s].y, wq.y);
                fma2(acck[s][cc], xq[s].x, wk.x);
                fma2(acck[s][cc], xq[s].y, wk.y);
            }
        }
    }

    float q[4][4], k[4][4];
#pragma unroll
    for (int s = 0; s < 4; s++)
#pragma unroll
        for (int c = 0; c < 4; c++) {
            q[s][c] = hsum2(accq[s][c]) * 0.25f;
            k[s][c] = hsum2(acck[s][c]);
        }

    // ---- scores + softmax ----
    float att[4][4];
#pragma unroll
    for (int qi = 0; qi < 4; qi++)
#pragma unroll
        for (int si = 0; si < 4; si++) {
            float p = q[qi][0] * k[si][0] + q[qi][1] * k[si][1] +
                      q[qi][2] * k[si][2] + q[qi][3] * k[si][3];
            p += __shfl_xor_sync(0xFFFFFFFFu, p, 1);
            p += __shfl_xor_sync(0xFFFFFFFFu, p, 2);
            att[qi][si] = p;
        }
#pragma unroll
    for (int qi = 0; qi < 4; qi++) {
        float m = fmaxf(fmaxf(att[qi][0], att[qi][1]), fmaxf(att[qi][2], att[qi][3]));
        float e0 = __expf(att[qi][0] - m);
        float e1 = __expf(att[qi][1] - m);
        float e2 = __expf(att[qi][2] - m);
        float e3 = __expf(att[qi][3] - m);
        float inv = 1.0f / (e0 + e1 + e2 + e3);
        att[qi][0] = e0 * inv; att[qi][1] = e1 * inv;
        att[qi][2] = e2 * inv; att[qi][3] = e3 * inv;
    }

    // ---- Phase B: v ----
    unsigned long long accv[4][4];
#pragma unroll
    for (int s = 0; s < 4; s++)
#pragma unroll
        for (int c = 0; c < 4; c++) accv[s][c] = 0ull;

#pragma unroll 4
    for (int dq = 0; dq < 64; dq += 4) {
        ulonglong2 xq[4];
#pragma unroll
        for (int s = 0; s < 4; s++)
            xq[s] = *(const ulonglong2*)(xrow + s * 64 + dq);
        int dsw = dq ^ fsw;
#pragma unroll
        for (int cc = 0; cc < 4; cc++) {
            ulonglong2 wv = *(const ulonglong2*)(sm + SW_V + wbase + cc * WT_STRIDE + dsw);
#pragma unroll
            for (int s = 0; s < 4; s++) {
                fma2(accv[s][cc], xq[s].x, wv.x);
                fma2(accv[s][cc], xq[s].y, wv.y);
            }
        }
    }
    float v[4][4];
#pragma unroll
    for (int s = 0; s < 4; s++)
#pragma unroll
        for (int c = 0; c < 4; c++) v[s][c] = hsum2(accv[s][c]);

    float o[4][4];
#pragma unroll
    for (int qi = 0; qi < 4; qi++)
#pragma unroll
        for (int c = 0; c < 4; c++)
            o[qi][c] = att[qi][0] * v[0][c] + att[qi][1] * v[1][c] +
                       att[qi][2] * v[2][c] + att[qi][3] * v[3][c];

    __syncwarp();
#pragma unroll
    for (int s = 0; s < 4; s++)
        *(float4*)(xrow + s * 64 + j0) = make_float4(o[s][0], o[s][1], o[s][2], o[s][3]);
    __syncwarp();

    // ---- Phase C: o @ Wo ----
    unsigned long long acco[4][4];
#pragma unroll
    for (int s = 0; s < 4; s++)
#pragma unroll
        for (int c = 0; c < 4; c++) acco[s][c] = 0ull;

#pragma unroll 4
    for (int dq = 0; dq < 64; dq += 4) {
        ulonglong2 xq[4];
#pragma unroll
        for (int s = 0; s < 4; s++)
            xq[s] = *(const ulonglong2*)(xrow + s * 64 + dq);
        int dsw = dq ^ fsw;
#pragma unroll
        for (int cc = 0; cc < 4; cc++) {
            ulonglong2 wo = *(const ulonglong2*)(sm + SW_O + wbase + cc * WT_STRIDE + dsw);
#pragma unroll
            for (int s = 0; s < 4; s++) {
                fma2(acco[s][cc], xq[s].x, wo.x);
                fma2(acco[s][cc], xq[s].y, wo.y);
            }
        }
    }

    // ---- epilogue: h_new, write g_h ----
    size_t base = (size_t)(nodeBase + nl) * NODE_F;
    float r[4][4];
#pragma unroll
    for (int s = 0; s < 4; s++) {
        r[s][0] = hsum2(acco[s][0]); r[s][1] = hsum2(acco[s][1]);
        r[s][2] = hsum2(acco[s][2]); r[s][3] = hsum2(acco[s][3]);
        if (RES) {
            float4 hold = *(const float4*)(g_h + base + s * 64 + j0);
            r[s][0] += hold.x + xin[s * 64 + j0 + 0];
            r[s][1] += hold.y + xin[s * 64 + j0 + 1];
            r[s][2] += hold.z + xin[s * 64 + j0 + 2];
            r[s][3] += hold.w + xin[s * 64 + j0 + 3];
        }
        *(float4*)(g_h + base + s * 64 + j0) = make_float4(r[s][0], r[s][1], r[s][2], r[s][3]);
    }

    // ---- relu + LN2 stats (and LN1 stats) across the node's 16 threads ----
    float rr[4][4];
    float ps[4] = {0, 0, 0, 0}, pq[4] = {0, 0, 0, 0};
    float ps1[4] = {0, 0, 0, 0}, pq1[4] = {0, 0, 0, 0};
#pragma unroll
    for (int s = 0; s < 4; s++)
#pragma unroll
        for (int c = 0; c < 4; c++) {
            float rv = fmaxf(r[s][c], 0.f);
            rr[s][c] = rv;
            ps[s] += rv; pq[s] += rv * rv;
            if (DO_LN1) { ps1[s] += r[s][c]; pq1[s] += r[s][c] * r[s][c]; }
        }
#pragma unroll
    for (int off = 1; off < 16; off <<= 1) {
#pragma unroll
        for (int s = 0; s < 4; s++) {
            ps[s] += __shfl_xor_sync(0xFFFFFFFFu, ps[s], off);
            pq[s] += __shfl_xor_sync(0xFFFFFFFFu, pq[s], off);
            if (DO_LN1) {
                ps1[s] += __shfl_xor_sync(0xFFFFFFFFu, ps1[s], off);
                pq1[s] += __shfl_xor_sync(0xFFFFFFFFu, pq1[s], off);
            }
        }
    }

    float g2c[4], b2c[4], g1c[4], b1c[4];
#pragma unroll
    for (int c = 0; c < 4; c++) {
        g2c[c] = __ldg(g2w + j0 + c);
        b2c[c] = __ldg(b2w + j0 + c);
        if (DO_LN1) { g1c[c] = __ldg(g1w + j0 + c); b1c[c] = __ldg(b1w + j0 + c); }
    }

#pragma unroll
    for (int s = 0; s < 4; s++) {
        float mu = ps[s] * (1.0f / 64.0f);
        float rstd = rsqrtf(pq[s] * (1.0f / 64.0f) - mu * mu + 1e-5f);
        float4 y;
        y.x = (rr[s][0] - mu) * rstd * g2c[0] + b2c[0];
        y.y = (rr[s][1] - mu) * rstd * g2c[1] + b2c[1];
        y.z = (rr[s][2] - mu) * rstd * g2c[2] + b2c[2];
        y.w = (rr[s][3] - mu) * rstd * g2c[3] + b2c[3];
        *(float4*)(xrow + s * 64 + j0) = y;   // stage LN2 output for pooling
        if (DO_LN1) {
            float mu1 = ps1[s] * (1.0f / 64.0f);
            float rstd1 = rsqrtf(pq1[s] * (1.0f / 64.0f) - mu1 * mu1 + 1e-5f);
            float4 hp;
            hp.x = (r[s][0] - mu1) * rstd1 * g1c[0] + b1c[0];
            hp.y = (r[s][1] - mu1) * rstd1 * g1c[1] + b1c[1];
            hp.z = (r[s][2] - mu1) * rstd1 * g1c[2] + b1c[2];
            hp.w = (r[s][3] - mu1) * rstd1 * g1c[3] + b1c[3];
            *(float4*)(hpre_out + base + s * 64 + j0) = hp;
        }
    }
    __syncthreads();

    // ---- block pooling over the 16 nodes -> RED ----
    int s2 = tid >> 6, d = tid & 63;
    float* poolBase = g_pooled + (size_t)layer * (N_GRAPHS * NODE_F);
    if (sgid[0] == sgid[15]) {
        float acc = 0.f;
#pragma unroll
        for (int n = 0; n < 16; n++) acc += sY[n * 264 + s2 * 64 + d];
        red_add_f1(poolBase + sgid[0] * NODE_F + s2 * 64 + d, acc);
    } else {
#pragma unroll 4
        for (int n = 0; n < 16; n++)
            red_add_f1(poolBase + sgid[n] * NODE_F + s2 * 64 + d,
                       sY[n * 264 + s2 * 64 + d]);
    }
}

// ---------------- final head ----------------
__global__ void score_kernel(const float* __restrict__ Wp,
                             const float* __restrict__ bp,
                             float* __restrict__ out) {
    int g = blockIdx.x;
    int t = threadIdx.x;
    int s = t >> 4, o = t & 15;
    float acc = 0.0f;
#pragma unroll
    for (int i = 0; i < 4; i++) {
        acc += __ldg(bp + i * 16 + o);
        const float* p = g_pooled + (size_t)i * (N_GRAPHS * NODE_F) + g * NODE_F + s * 64;
        const float* wp = Wp + i * 1024 + o;
        float a2 = 0.0f;
#pragma unroll 8
        for (int d = 0; d < 64; d++) a2 += p[d] * __ldg(wp + d * 16);
        acc += a2;
    }
    out[g * 64 + s * 16 + o] = acc;
}

// ---------------- launch ----------------
extern "C" void kernel_launch(void* const* d_in, const int* in_sizes, int n_in,
                              void* d_out, int out_size) {
    const float* feat = (const float*)d_in[0];
    const int*   src  = (const int*)d_in[1];
    const int*   dst  = (const int*)d_in[2];
    const int*   gids = (const int*)d_in[3];
    const float* Wq   = (const float*)d_in[4];
    const float* Wk   = (const float*)d_in[5];
    const float* Wv   = (const float*)d_in[6];
    const float* Wo   = (const float*)d_in[7];
    const float* slng = (const float*)d_in[8];
    const float* slnb = (const float*)d_in[9];
    const float* ln1g = (const float*)d_in[10];
    const float* ln1b = (const float*)d_in[11];
    const float* ln2g = (const float*)d_in[12];
    const float* ln2b = (const float*)d_in[13];
    const float* Wp   = (const float*)d_in[14];
    const float* bp   = (const float*)d_in[15];
    float* out = (float*)d_out;

    const int smem = FUSED_SMEM_FLOATS * 4;   // ~104 KB -> 2 CTAs/SM
    cudaFuncSetAttribute(fused_layer_kernel<false, true>,
                         cudaFuncAttributeMaxDynamicSharedMemorySize, smem);
    cudaFuncSetAttribute(fused_layer_kernel<true, true>,
                         cudaFuncAttributeMaxDynamicSharedMemorySize, smem);
    cudaFuncSetAttribute(fused_layer_kernel<true, false>,
                         cudaFuncAttributeMaxDynamicSharedMemorySize, smem);

    void* hpreA = nullptr;
    void* hpreB = nullptr;
    cudaGetSymbolAddress(&hpreA, g_hpreA);
    cudaGetSymbolAddress(&hpreB, g_hpreB);

    // ---- CSR build + init ----
    zeros_kernel<<<512, 256>>>();
    hist_kernel<<<3125, 256>>>(dst);
    scanA_kernel<<<NB_SCAN, 256>>>();
    scanB_kernel<<<1, 256>>>();
    scanC_kernel<<<NB_SCAN, 256>>>();
    fill_kernel<<<3125, 256>>>(src, dst);

    // hidden_rep[0]: raw feature pooling
    pool_raw_kernel<<<3125, 256>>>(feat, gids);

    // ---- fused layers (hpre ping-pong: feat -> A -> B) ----
    fused_layer_kernel<false, true><<<3125, 256, smem>>>(
        feat, (float*)hpreA, Wq, Wk, Wv, Wo, slng, slnb,
        ln2g, ln2b, ln1g + 64, ln1b + 64, gids, 1);

    fused_layer_kernel<true, true><<<3125, 256, smem>>>(
        (const float*)hpreA, (float*)hpreB,
        Wq + 4096, Wk + 4096, Wv + 4096, Wo + 4096,
        slng + 64, slnb + 64, ln2g + 64, ln2b + 64,
        ln1g + 128, ln1b + 128, gids, 2);

    fused_layer_kernel<true, false><<<3125, 256, smem>>>(
        (const float*)hpreB, nullptr,
        Wq + 8192, Wk + 8192, Wv + 8192, Wo + 8192,
        slng + 128, slnb + 128, ln2g + 128, ln2b + 128,
        nullptr, nullptr, gids, 3);

    // ---- head ----
    score_kernel<<<N_GRAPHS, 64>>>(Wp, bp, out);
}